// round 1
// baseline (speedup 1.0000x reference)
#include <cuda_runtime.h>
#include <math.h>

#define DD 1024
#define B_ROWS 128
#define C_ROWS 1000
#define N_ROWS (B_ROWS + C_ROWS)   // 1128
#define EPSF 1e-6f

// Scratch (no cudaMalloc allowed)
__device__ float g_Y[B_ROWS * DD];    // x @ tril(L)
__device__ float g_M[C_ROWS * DD];    // mu @ tril(L)
__device__ float g_nP[B_ROWS];        // ||y_b||^2 + eps*||x_b||^2
__device__ float g_bx[B_ROWS];        // beta . x_b
__device__ float g_nQ[C_ROWS];        // ||m_c||^2 + eps*||mu_c||^2
__device__ float g_bm[C_ROWS];        // beta . mu_c

// ---------------------------------------------------------------------------
// Kernel 1: Z = A @ tril(L), A = [x; mu] (1128 x 1024). 64x64 tile, BK=16.
// Triangular skip: column tile [colBase, colBase+64) only needs k >= colBase.
// ---------------------------------------------------------------------------
__global__ __launch_bounds__(256) void k_gemm_ALt(
    const float* __restrict__ x, const float* __restrict__ mu,
    const float* __restrict__ L) {
    constexpr int BM = 64, BN = 64, BK = 16;
    __shared__ float As[BK][BM + 1];
    __shared__ float Bs[BK][BN + 4];

    const int tid = threadIdx.x;
    const int rowBase = blockIdx.y * BM;
    const int colBase = blockIdx.x * BN;
    const int ty = tid / 16, tx = tid % 16;

    float acc[4][4] = {};

    // tril: contributions only from k >= col, so start K-loop at colBase.
    for (int k0 = colBase; k0 < DD; k0 += BK) {
        // Load A tile (64x16), 4 elems/thread, coalesced over k.
        #pragma unroll
        for (int i = 0; i < 4; i++) {
            int idx = tid + i * 256;
            int r = idx / BK;
            int k = idx % BK;
            int gr = rowBase + r;
            float v = 0.f;
            if (gr < B_ROWS)        v = x[gr * DD + k0 + k];
            else if (gr < N_ROWS)   v = mu[(gr - B_ROWS) * DD + k0 + k];
            As[k][r] = v;
        }
        // Load B tile = tril(L)[k0:k0+16, colBase:colBase+64], float4 + mask.
        {
            int k = tid / 16;
            int c = (tid % 16) * 4;
            int gk = k0 + k;
            const float4 lv = *reinterpret_cast<const float4*>(
                &L[(size_t)gk * DD + colBase + c]);
            float4 bv;
            bv.x = (gk >= colBase + c + 0) ? lv.x : 0.f;
            bv.y = (gk >= colBase + c + 1) ? lv.y : 0.f;
            bv.z = (gk >= colBase + c + 2) ? lv.z : 0.f;
            bv.w = (gk >= colBase + c + 3) ? lv.w : 0.f;
            *reinterpret_cast<float4*>(&Bs[k][c]) = bv;
        }
        __syncthreads();

        #pragma unroll
        for (int kk = 0; kk < BK; kk++) {
            float a[4], b[4];
            #pragma unroll
            for (int i = 0; i < 4; i++) a[i] = As[kk][ty * 4 + i];
            #pragma unroll
            for (int j = 0; j < 4; j++) b[j] = Bs[kk][tx * 4 + j];
            #pragma unroll
            for (int i = 0; i < 4; i++)
                #pragma unroll
                for (int j = 0; j < 4; j++) acc[i][j] += a[i] * b[j];
        }
        __syncthreads();
    }

    #pragma unroll
    for (int i = 0; i < 4; i++) {
        int gr = rowBase + ty * 4 + i;
        if (gr >= N_ROWS) continue;
        float* dst = (gr < B_ROWS) ? &g_Y[gr * DD]
                                   : &g_M[(size_t)(gr - B_ROWS) * DD];
        #pragma unroll
        for (int j = 0; j < 4; j++)
            dst[colBase + tx * 4 + j] = acc[i][j];
    }
}

// ---------------------------------------------------------------------------
// Kernel 2: per-row stats. One block per row of [x;mu] / [Y;M].
// ---------------------------------------------------------------------------
__global__ __launch_bounds__(256) void k_rowstats(
    const float* __restrict__ x, const float* __restrict__ mu,
    const float* __restrict__ beta) {
    const int r = blockIdx.x;
    const int tid = threadIdx.x;
    const float* zrow;
    const float* arow;
    if (r < B_ROWS) { zrow = &g_Y[r * DD]; arow = &x[r * DD]; }
    else            { zrow = &g_M[(size_t)(r - B_ROWS) * DD];
                      arow = &mu[(size_t)(r - B_ROWS) * DD]; }

    float sz = 0.f, sa = 0.f, sb = 0.f;
    for (int k = tid; k < DD; k += 256) {
        float z = zrow[k], a = arow[k], bt = beta[k];
        sz += z * z;
        sa += a * a;
        sb += bt * a;
    }
    // reduce
    #pragma unroll
    for (int off = 16; off; off >>= 1) {
        sz += __shfl_down_sync(0xffffffffu, sz, off);
        sa += __shfl_down_sync(0xffffffffu, sa, off);
        sb += __shfl_down_sync(0xffffffffu, sb, off);
    }
    __shared__ float red[3][8];
    int w = tid / 32, lane = tid % 32;
    if (lane == 0) { red[0][w] = sz; red[1][w] = sa; red[2][w] = sb; }
    __syncthreads();
    if (tid == 0) {
        float SZ = 0.f, SA = 0.f, SB = 0.f;
        #pragma unroll
        for (int i = 0; i < 8; i++) { SZ += red[0][i]; SA += red[1][i]; SB += red[2][i]; }
        float n = SZ + EPSF * SA;
        if (r < B_ROWS) { g_nP[r] = n; g_bx[r] = SB; }
        else            { g_nQ[r - B_ROWS] = n; g_bm[r - B_ROWS] = SB; }
    }
}

// ---------------------------------------------------------------------------
// Kernel 3: G[b,c] = Y_b . M_c + eps * x_b . mu_c (NT GEMM, K=1024 twice),
// fused epilogue -> out. Tile 32(b) x 64(c), BK=16, 256 threads, 2x4 micro.
// ---------------------------------------------------------------------------
__global__ __launch_bounds__(256) void k_out(
    const float* __restrict__ x, const float* __restrict__ mu,
    const float* __restrict__ lmbda_p, const float* __restrict__ scale_p,
    float* __restrict__ out) {
    constexpr int BM = 32, BN = 64, BK = 16;
    __shared__ float As[BK][BM + 1];
    __shared__ float Bs[BK][BN + 1];

    const int tid = threadIdx.x;
    const int ty = tid / 16, tx = tid % 16;
    const int rowBase = blockIdx.y * BM;   // b
    const int colBase = blockIdx.x * BN;   // c

    float acc1[2][4] = {};
    float acc2[2][4] = {};

    #pragma unroll
    for (int phase = 0; phase < 2; phase++) {
        const float* A  = phase ? x  : g_Y;   // [128,  D]
        const float* Bm = phase ? mu : g_M;   // [1000, D]
        for (int k0 = 0; k0 < DD; k0 += BK) {
            // A tile: 32x16 = 512 elems, 2/thread
            #pragma unroll
            for (int i = 0; i < 2; i++) {
                int idx = tid + i * 256;
                int r = idx / BK, k = idx % BK;
                As[k][r] = A[(size_t)(rowBase + r) * DD + k0 + k];
            }
            // B tile: 64x16 = 1024 elems, 4/thread
            #pragma unroll
            for (int i = 0; i < 4; i++) {
                int idx = tid + i * 256;
                int c = idx / BK, k = idx % BK;
                int gc = colBase + c;
                Bs[k][c] = (gc < C_ROWS) ? Bm[(size_t)gc * DD + k0 + k] : 0.f;
            }
            __syncthreads();
            #pragma unroll
            for (int kk = 0; kk < BK; kk++) {
                float a[2], b[4];
                #pragma unroll
                for (int i = 0; i < 2; i++) a[i] = As[kk][ty * 2 + i];
                #pragma unroll
                for (int j = 0; j < 4; j++) b[j] = Bs[kk][tx * 4 + j];
                #pragma unroll
                for (int i = 0; i < 2; i++)
                    #pragma unroll
                    for (int j = 0; j < 4; j++) {
                        if (phase == 0) acc1[i][j] += a[i] * b[j];
                        else            acc2[i][j] += a[i] * b[j];
                    }
            }
            __syncthreads();
        }
    }

    const float lmbda = *lmbda_p;
    const float scale = *scale_p;
    #pragma unroll
    for (int i = 0; i < 2; i++) {
        int b = rowBase + ty * 2 + i;
        float np = g_nP[b];
        float bx = g_bx[b];
        #pragma unroll
        for (int j = 0; j < 4; j++) {
            int c = colBase + tx * 4 + j;
            if (c < C_ROWS) {
                float G = acc1[i][j] + EPSF * acc2[i][j];
                float quad = np + g_nQ[c] - 2.f * G;
                float bd = bx - g_bm[c];
                out[(size_t)b * C_ROWS + c] =
                    -scale * (sqrtf(quad + EPSF) + lmbda * sqrtf(bd * bd + EPSF));
            }
        }
    }
}

// ---------------------------------------------------------------------------
extern "C" void kernel_launch(void* const* d_in, const int* in_sizes, int n_in,
                              void* d_out, int out_size) {
    const float* x     = (const float*)d_in[0];
    const float* mu    = (const float*)d_in[1];
    const float* beta  = (const float*)d_in[2];
    const float* L     = (const float*)d_in[3];
    const float* lmbda = (const float*)d_in[4];
    const float* scale = (const float*)d_in[5];
    float* out = (float*)d_out;

    dim3 g1(DD / 64, (N_ROWS + 63) / 64);          // 16 x 18
    k_gemm_ALt<<<g1, 256>>>(x, mu, L);

    k_rowstats<<<N_ROWS, 256>>>(x, mu, beta);

    dim3 g3((C_ROWS + 63) / 64, B_ROWS / 32);      // 16 x 4
    k_out<<<g3, 256>>>(x, mu, lmbda, scale, out);
}

// round 3
// speedup vs baseline: 2.2880x; 2.2880x over previous
#include <cuda_runtime.h>
#include <math.h>

#define DD 1024
#define B_ROWS 128
#define C_ROWS 1000
#define N_ROWS (B_ROWS + C_ROWS)   // 1128
#define EPSF 1e-6f

// Scratch (no cudaMalloc allowed)
__device__ float g_Y[B_ROWS * DD];    // x @ tril(L)
__device__ float g_M[C_ROWS * DD];    // mu @ tril(L)
__device__ float g_nP[B_ROWS];        // ||y_b||^2 + eps*||x_b||^2
__device__ float g_bx[B_ROWS];        // beta . x_b
__device__ float g_nQ[C_ROWS];        // ||m_c||^2 + eps*||mu_c||^2
__device__ float g_bm[C_ROWS];        // beta . mu_c

// ---------------------------------------------------------------------------
// Kernel 1: Z = A @ tril(L), A = [x; mu] (1128 x 1024).
// Pair-balanced triangular skip: block handles col tiles {p, 15-p}; their
// K-lengths (1024-64p) + (64p+64) = 1088 are constant -> uniform blocks.
// BM=32, BN=64, BK=16, 128 threads, 4x4 microtile.
// ---------------------------------------------------------------------------
__global__ __launch_bounds__(128) void k_gemm_ALt(
    const float* __restrict__ x, const float* __restrict__ mu,
    const float* __restrict__ L) {
    constexpr int BM = 32, BN = 64, BK = 16;
    __shared__ float As[BK][BM + 4];   // stride 36 floats (16B aligned rows)
    __shared__ float Bs[BK][BN + 4];   // stride 68 floats (16B aligned rows)

    const int tid = threadIdx.x;
    const int rowBase = blockIdx.y * BM;
    const int pair = blockIdx.x;              // 0..7
    const int ry = tid >> 4;                  // 0..7  (4 rows each)
    const int cx = tid & 15;                  // 0..15 (4 cols each)

    #pragma unroll
    for (int phase = 0; phase < 2; phase++) {
        const int ct = phase == 0 ? pair : 15 - pair;
        const int colBase = ct * 64;
        float acc[4][4] = {};

        for (int k0 = colBase; k0 < DD; k0 += BK) {
            // A tile: 32x16 = 512 elems, 4/thread via float4 over k.
            {
                int r  = tid >> 2;            // 0..31
                int kc = (tid & 3) * 4;       // 0,4,8,12
                int gr = rowBase + r;
                float4 v = make_float4(0.f, 0.f, 0.f, 0.f);
                if (gr < B_ROWS)
                    v = *reinterpret_cast<const float4*>(&x[(size_t)gr * DD + k0 + kc]);
                else if (gr < N_ROWS)
                    v = *reinterpret_cast<const float4*>(&mu[(size_t)(gr - B_ROWS) * DD + k0 + kc]);
                As[kc + 0][r] = v.x;
                As[kc + 1][r] = v.y;
                As[kc + 2][r] = v.z;
                As[kc + 3][r] = v.w;
            }
            // B tile = tril(L)[k0:k0+16, colBase:colBase+64]: 256 float4, 2/thread.
            #pragma unroll
            for (int i = 0; i < 2; i++) {
                int idx = tid + i * 128;      // 0..255
                int k   = idx >> 4;
                int c4  = (idx & 15) * 4;
                int gk  = k0 + k;
                const float4 lv = *reinterpret_cast<const float4*>(
                    &L[(size_t)gk * DD + colBase + c4]);
                float4 bv;
                bv.x = (gk >= colBase + c4 + 0) ? lv.x : 0.f;
                bv.y = (gk >= colBase + c4 + 1) ? lv.y : 0.f;
                bv.z = (gk >= colBase + c4 + 2) ? lv.z : 0.f;
                bv.w = (gk >= colBase + c4 + 3) ? lv.w : 0.f;
                *reinterpret_cast<float4*>(&Bs[k][c4]) = bv;
            }
            __syncthreads();

            #pragma unroll
            for (int kk = 0; kk < BK; kk++) {
                float4 a = *reinterpret_cast<const float4*>(&As[kk][ry * 4]);
                float4 b = *reinterpret_cast<const float4*>(&Bs[kk][cx * 4]);
                float av[4] = {a.x, a.y, a.z, a.w};
                float bv[4] = {b.x, b.y, b.z, b.w};
                #pragma unroll
                for (int i = 0; i < 4; i++)
                    #pragma unroll
                    for (int j = 0; j < 4; j++) acc[i][j] += av[i] * bv[j];
            }
            __syncthreads();
        }

        #pragma unroll
        for (int i = 0; i < 4; i++) {
            int gr = rowBase + ry * 4 + i;
            if (gr >= N_ROWS) continue;
            float* dst = (gr < B_ROWS) ? &g_Y[(size_t)gr * DD]
                                       : &g_M[(size_t)(gr - B_ROWS) * DD];
            *reinterpret_cast<float4*>(&dst[colBase + cx * 4]) =
                make_float4(acc[i][0], acc[i][1], acc[i][2], acc[i][3]);
        }
        __syncthreads();
    }
}

// ---------------------------------------------------------------------------
// Kernel 2: per-row stats. One block per row of [x;mu] / [Y;M].
// ---------------------------------------------------------------------------
__global__ __launch_bounds__(256) void k_rowstats(
    const float* __restrict__ x, const float* __restrict__ mu,
    const float* __restrict__ beta) {
    const int r = blockIdx.x;
    const int tid = threadIdx.x;
    const float* zrow;
    const float* arow;
    if (r < B_ROWS) { zrow = &g_Y[(size_t)r * DD]; arow = &x[(size_t)r * DD]; }
    else            { zrow = &g_M[(size_t)(r - B_ROWS) * DD];
                      arow = &mu[(size_t)(r - B_ROWS) * DD]; }

    float sz = 0.f, sa = 0.f, sb = 0.f;
    for (int k = tid; k < DD; k += 256) {
        float z = zrow[k], a = arow[k], bt = beta[k];
        sz += z * z;
        sa += a * a;
        sb += bt * a;
    }
    #pragma unroll
    for (int off = 16; off; off >>= 1) {
        sz += __shfl_down_sync(0xffffffffu, sz, off);
        sa += __shfl_down_sync(0xffffffffu, sa, off);
        sb += __shfl_down_sync(0xffffffffu, sb, off);
    }
    __shared__ float red[3][8];
    int w = tid / 32, lane = tid % 32;
    if (lane == 0) { red[0][w] = sz; red[1][w] = sa; red[2][w] = sb; }
    __syncthreads();
    if (tid == 0) {
        float SZ = 0.f, SA = 0.f, SB = 0.f;
        #pragma unroll
        for (int i = 0; i < 8; i++) { SZ += red[0][i]; SA += red[1][i]; SB += red[2][i]; }
        float n = SZ + EPSF * SA;
        if (r < B_ROWS) { g_nP[r] = n; g_bx[r] = SB; }
        else            { g_nQ[r - B_ROWS] = n; g_bm[r - B_ROWS] = SB; }
    }
}

// ---------------------------------------------------------------------------
// Kernel 3: G[b,c] = Y_b . M_c (NT GEMM, K=1024), fused epilogue -> out.
// (eps * x.mu cross term dropped: contributes <1e-8 relative to output.)
// BM=32 (b) x BN=32 (c), BK=32, 128 threads, 2x4 microtile. Grid 32x4 = 128.
// ---------------------------------------------------------------------------
__global__ __launch_bounds__(128) void k_out(
    const float* __restrict__ lmbda_p, const float* __restrict__ scale_p,
    float* __restrict__ out) {
    constexpr int BM = 32, BN = 32, BK = 32;
    __shared__ float As[BK][BM + 4];   // stride 36
    __shared__ float Bs[BK][BN + 4];   // stride 36

    const int tid = threadIdx.x;
    const int ry = tid >> 3;           // 0..15 (2 rows each)
    const int cx = tid & 7;            // 0..7  (4 cols each)
    const int rowBase = blockIdx.y * BM;   // b
    const int colBase = blockIdx.x * BN;   // c

    float acc[2][4] = {};

    for (int k0 = 0; k0 < DD; k0 += BK) {
        // A tile: Y[rowBase:+32, k0:+32] = 1024 elems, 8/thread (2 float4 over k)
        #pragma unroll
        for (int i = 0; i < 2; i++) {
            int idx = tid + i * 128;       // 0..255 (float4 units)
            int r   = idx >> 3;            // 0..31
            int kc  = (idx & 7) * 4;       // 0..28
            float4 v = *reinterpret_cast<const float4*>(
                &g_Y[(size_t)(rowBase + r) * DD + k0 + kc]);
            As[kc + 0][r] = v.x;
            As[kc + 1][r] = v.y;
            As[kc + 2][r] = v.z;
            As[kc + 3][r] = v.w;
        }
        // B tile: M[colBase:+32, k0:+32] (NT: rows are classes)
        #pragma unroll
        for (int i = 0; i < 2; i++) {
            int idx = tid + i * 128;
            int c   = idx >> 3;
            int kc  = (idx & 7) * 4;
            int gc  = colBase + c;
            float4 v = make_float4(0.f, 0.f, 0.f, 0.f);
            if (gc < C_ROWS)
                v = *reinterpret_cast<const float4*>(
                    &g_M[(size_t)gc * DD + k0 + kc]);
            Bs[kc + 0][c] = v.x;
            Bs[kc + 1][c] = v.y;
            Bs[kc + 2][c] = v.z;
            Bs[kc + 3][c] = v.w;
        }
        __syncthreads();

        #pragma unroll
        for (int kk = 0; kk < BK; kk++) {
            float a0 = As[kk][ry * 2 + 0];
            float a1 = As[kk][ry * 2 + 1];
            float4 b = *reinterpret_cast<const float4*>(&Bs[kk][cx * 4]);
            float bv[4] = {b.x, b.y, b.z, b.w};
            #pragma unroll
            for (int j = 0; j < 4; j++) {
                acc[0][j] += a0 * bv[j];
                acc[1][j] += a1 * bv[j];
            }
        }
        __syncthreads();
    }

    const float lmbda = *lmbda_p;
    const float scale = *scale_p;
    #pragma unroll
    for (int i = 0; i < 2; i++) {
        int b = rowBase + ry * 2 + i;
        float np = g_nP[b];
        float bx = g_bx[b];
        #pragma unroll
        for (int j = 0; j < 4; j++) {
            int c = colBase + cx * 4 + j;
            if (c < C_ROWS) {
                float quad = np + g_nQ[c] - 2.f * acc[i][j];
                float bd = bx - g_bm[c];
                out[(size_t)b * C_ROWS + c] =
                    -scale * (sqrtf(quad + EPSF) + lmbda * sqrtf(bd * bd + EPSF));
            }
        }
    }
}

// ---------------------------------------------------------------------------
extern "C" void kernel_launch(void* const* d_in, const int* in_sizes, int n_in,
                              void* d_out, int out_size) {
    const float* x     = (const float*)d_in[0];
    const float* mu    = (const float*)d_in[1];
    const float* beta  = (const float*)d_in[2];
    const float* L     = (const float*)d_in[3];
    const float* lmbda = (const float*)d_in[4];
    const float* scale = (const float*)d_in[5];
    float* out = (float*)d_out;

    dim3 g1(8, (N_ROWS + 31) / 32);                // 8 pairs x 36 row tiles
    k_gemm_ALt<<<g1, 128>>>(x, mu, L);

    k_rowstats<<<N_ROWS, 256>>>(x, mu, beta);

    dim3 g3((C_ROWS + 31) / 32, B_ROWS / 32);      // 32 x 4 = 128 blocks
    k_out<<<g3, 128>>>(lmbda, scale, out);
}

// round 6
// speedup vs baseline: 3.6046x; 1.5755x over previous
#include <cuda_runtime.h>
#include <cuda_bf16.h>
#include <cstdint>
#include <math.h>

#define DD 1024
#define B_ROWS 128
#define C_ROWS 1000
#define N_ROWS (B_ROWS + C_ROWS)   // 1128
#define N_PAD 1152                 // 18 * 64
#define EPSF 1e-6f

// ---------------- scratch (__device__, no cudaMalloc) ----------------
__device__ float g_Y[B_ROWS * DD];            // x @ tril(L)   (fp32)
__device__ float g_M[C_ROWS * DD];            // mu @ tril(L)  (fp32)
__device__ float g_nP[B_ROWS];
__device__ float g_bx[B_ROWS];
__device__ float g_nQ[C_ROWS];
__device__ float g_bm[C_ROWS];
__device__ __nv_bfloat16 g_Ah[N_PAD * DD];    // [x;mu] hi bf16 (padded rows zero)
__device__ __nv_bfloat16 g_Al[N_PAD * DD];    // [x;mu] lo bf16
__device__ __nv_bfloat16 g_BhT[DD * DD];      // tril(L)^T hi: g_BhT[col][k] = trilL[k][col]
__device__ __nv_bfloat16 g_BlT[DD * DD];      // tril(L)^T lo

// ---------------- helpers (family-generic PTX only: sm_80-era) ----------------
__device__ __forceinline__ uint32_t smem_to_u32(const void* p) {
    uint32_t a;
    asm("{ .reg .u64 t; cvta.to.shared.u64 t, %1; cvt.u32.u64 %0, t; }"
        : "=r"(a) : "l"(p));
    return a;
}

#define CP16(dst, src) \
    asm volatile("cp.async.cg.shared.global [%0], [%1], 16;" \
        :: "r"(dst), "l"(src) : "memory")
#define CP_COMMIT() asm volatile("cp.async.commit_group;" ::: "memory")
#define CP_WAIT0()  asm volatile("cp.async.wait_group 0;" ::: "memory")

#define LDSM4(r0, r1, r2, r3, addr) \
    asm volatile("ldmatrix.sync.aligned.m8n8.x4.shared.b16 {%0,%1,%2,%3}, [%4];" \
        : "=r"(r0), "=r"(r1), "=r"(r2), "=r"(r3) : "r"(addr))

#define MMA16816(d, a, b) \
    asm volatile("mma.sync.aligned.m16n8k16.row.col.f32.bf16.bf16.f32 " \
        "{%0,%1,%2,%3}, {%4,%5,%6,%7}, {%8,%9}, {%0,%1,%2,%3};" \
        : "+f"((d)[0]), "+f"((d)[1]), "+f"((d)[2]), "+f"((d)[3]) \
        : "r"((a)[0]), "r"((a)[1]), "r"((a)[2]), "r"((a)[3]), \
          "r"((b)[0]), "r"((b)[1]))

// ---------------------------------------------------------------------------
// Conversion: [x;mu] (padded to 1152 rows) -> bf16 hi/lo
// ---------------------------------------------------------------------------
__global__ __launch_bounds__(256) void conv_A(
    const float* __restrict__ x, const float* __restrict__ mu) {
    int idx = blockIdx.x * 256 + threadIdx.x;      // float4 index
    int row = idx >> 8;
    int c4  = (idx & 255) * 4;
    float4 v = make_float4(0.f, 0.f, 0.f, 0.f);
    if (row < B_ROWS)       v = *reinterpret_cast<const float4*>(&x[(size_t)row * DD + c4]);
    else if (row < N_ROWS)  v = *reinterpret_cast<const float4*>(&mu[(size_t)(row - B_ROWS) * DD + c4]);
    float vv[4] = {v.x, v.y, v.z, v.w};
    __nv_bfloat16 h[4], l[4];
    #pragma unroll
    for (int i = 0; i < 4; i++) {
        h[i] = __float2bfloat16_rn(vv[i]);
        l[i] = __float2bfloat16_rn(vv[i] - __bfloat162float(h[i]));
    }
    *reinterpret_cast<uint2*>(&g_Ah[(size_t)row * DD + c4]) = *reinterpret_cast<uint2*>(h);
    *reinterpret_cast<uint2*>(&g_Al[(size_t)row * DD + c4]) = *reinterpret_cast<uint2*>(l);
}

// ---------------------------------------------------------------------------
// Conversion: tril(L) masked, transposed, split hi/lo.  g_BhT[col][k].
// ---------------------------------------------------------------------------
__global__ __launch_bounds__(256) void conv_LT(const float* __restrict__ L) {
    __shared__ float tile[64][65];
    const int bR = blockIdx.y * 64;   // k base
    const int bC = blockIdx.x * 64;   // col base
    const int tid = threadIdx.x;

    #pragma unroll
    for (int i = 0; i < 16; i++) {
        int idx = tid + i * 256;
        int r = idx >> 6, c = idx & 63;
        float v = L[(size_t)(bR + r) * DD + bC + c];
        if (bC + c > bR + r) v = 0.f;   // tril mask
        tile[r][c] = v;
    }
    __syncthreads();
    #pragma unroll
    for (int i = 0; i < 16; i++) {
        int idx = tid + i * 256;
        int c = idx >> 6, r = idx & 63;
        float v = tile[r][c];
        __nv_bfloat16 h = __float2bfloat16_rn(v);
        __nv_bfloat16 l = __float2bfloat16_rn(v - __bfloat162float(h));
        size_t o = (size_t)(bC + c) * DD + bR + r;
        g_BhT[o] = h;
        g_BlT[o] = l;
    }
}

// ---------------------------------------------------------------------------
// Kernel 1 (warp MMA): Z = A @ tril(L), split-bf16 3-term (hh + hl + lh).
// BM=64, BN=64, BK=32, 128 threads (2x2 warps, warp tile 32x32).
// Pair-balanced tril skip: block does col tiles {p, 15-p}; K sums to 1088.
// smem tile row stride 40 bf16 (80 B) -> conflict-free ldmatrix.
// ---------------------------------------------------------------------------
#define TILE_B (64 * 40)          // bf16 elems per tile
#define STAGE_B (4 * TILE_B)      // Ah, Al, Bh, Bl

__global__ __launch_bounds__(128) void k1_mma() {
    __shared__ __align__(16) __nv_bfloat16 sm[2][STAGE_B];

    const int tid   = threadIdx.x;
    const int lane  = tid & 31;
    const int warp  = tid >> 5;
    const int warpm = warp & 1;
    const int warpn = warp >> 1;
    const int pairid  = blockIdx.x;        // 0..7
    const int rowBase = blockIdx.y * 64;   // 0..1088

    const uint32_t smbase = smem_to_u32(sm);

    #pragma unroll 1
    for (int phase = 0; phase < 2; phase++) {
        const int ct = phase ? (15 - pairid) : pairid;
        const int colBase = ct * 64;
        const int NIT = (DD - colBase) >> 5;     // K / 32

        // per-thread cp.async chunk mapping (8 chunks of 16B per stage)
        const __nv_bfloat16* srcb[8];
        uint32_t dsto[8];
        #pragma unroll
        for (int t = 0; t < 8; t++) {
            int tl  = t >> 1;
            int row = ((t & 1) << 5) + (tid >> 2);
            int c4  = tid & 3;
            const __nv_bfloat16* g;
            int grow;
            if      (tl == 0) { g = g_Ah;  grow = rowBase + row; }
            else if (tl == 1) { g = g_Al;  grow = rowBase + row; }
            else if (tl == 2) { g = g_BhT; grow = colBase + row; }
            else              { g = g_BlT; grow = colBase + row; }
            srcb[t] = g + (size_t)grow * DD + c4 * 8;
            dsto[t] = (uint32_t)(tl * (TILE_B * 2) + row * 80 + c4 * 16);
        }

        float acc[2][4][4];
        #pragma unroll
        for (int i = 0; i < 2; i++)
            #pragma unroll
            for (int j = 0; j < 4; j++)
                #pragma unroll
                for (int r = 0; r < 4; r++) acc[i][j][r] = 0.f;

        __syncthreads();   // protect smem reuse across phases

        // prefetch stage 0
        {
            uint32_t sb0 = smbase;
            #pragma unroll
            for (int t = 0; t < 8; t++) CP16(sb0 + dsto[t], srcb[t] + colBase);
            CP_COMMIT();
        }

        // ldmatrix per-lane address components (within a tile)
        const uint32_t a_row_off = (uint32_t)((warpm * 32 + (lane & 15)) * 80);
        const uint32_t b_row_off = (uint32_t)((warpn * 32 + (lane & 15)) * 80);
        const uint32_t k_lane_off = (uint32_t)(((lane >> 4) & 1) * 16);  // bytes

        for (int it = 0; it < NIT; it++) {
            CP_WAIT0();
            __syncthreads();
            if (it + 1 < NIT) {
                uint32_t sbn = smbase + ((it + 1) & 1) * (STAGE_B * 2);
                int k0 = colBase + (it + 1) * 32;
                #pragma unroll
                for (int t = 0; t < 8; t++) CP16(sbn + dsto[t], srcb[t] + k0);
                CP_COMMIT();
            }

            const uint32_t bufb = smbase + (it & 1) * (STAGE_B * 2);

            #pragma unroll
            for (int k16 = 0; k16 < 2; k16++) {
                const uint32_t kb = (uint32_t)(k16 * 32) + k_lane_off;  // byte k-offset

                uint32_t ah[2][4], al[2][4];
                #pragma unroll
                for (int mt = 0; mt < 2; mt++) {
                    uint32_t ad = bufb + a_row_off + (uint32_t)(mt * 16 * 80) + kb;
                    LDSM4(ah[mt][0], ah[mt][1], ah[mt][2], ah[mt][3], ad);
                    LDSM4(al[mt][0], al[mt][1], al[mt][2], al[mt][3], ad + TILE_B * 2);
                }
                uint32_t bh[4][2], bl[4][2];
                #pragma unroll
                for (int nt2 = 0; nt2 < 2; nt2++) {
                    uint32_t bd = bufb + 2 * (TILE_B * 2) + b_row_off
                                + (uint32_t)(nt2 * 16 * 80) + kb;
                    uint32_t r0, r1, r2, r3;
                    LDSM4(r0, r1, r2, r3, bd);
                    bh[nt2 * 2 + 0][0] = r0; bh[nt2 * 2 + 0][1] = r2;
                    bh[nt2 * 2 + 1][0] = r1; bh[nt2 * 2 + 1][1] = r3;
                    LDSM4(r0, r1, r2, r3, bd + TILE_B * 2);
                    bl[nt2 * 2 + 0][0] = r0; bl[nt2 * 2 + 0][1] = r2;
                    bl[nt2 * 2 + 1][0] = r1; bl[nt2 * 2 + 1][1] = r3;
                }
                #pragma unroll
                for (int mt = 0; mt < 2; mt++)
                    #pragma unroll
                    for (int nt = 0; nt < 4; nt++) {
                        MMA16816(acc[mt][nt], ah[mt], bh[nt]);
                        MMA16816(acc[mt][nt], ah[mt], bl[nt]);
                        MMA16816(acc[mt][nt], al[mt], bh[nt]);
                    }
            }
        }

        // epilogue: write fp32 Z tile
        #pragma unroll
        for (int mt = 0; mt < 2; mt++) {
            #pragma unroll
            for (int nt = 0; nt < 4; nt++) {
                int gm = rowBase + warpm * 32 + mt * 16 + (lane >> 2);
                int gn = colBase + warpn * 32 + nt * 8 + (lane & 3) * 2;
                #pragma unroll
                for (int h = 0; h < 2; h++) {
                    int gr = gm + h * 8;
                    float2 v = make_float2(acc[mt][nt][h * 2], acc[mt][nt][h * 2 + 1]);
                    if (gr < B_ROWS)
                        *reinterpret_cast<float2*>(&g_Y[(size_t)gr * DD + gn]) = v;
                    else if (gr < N_ROWS)
                        *reinterpret_cast<float2*>(&g_M[(size_t)(gr - B_ROWS) * DD + gn]) = v;
                }
            }
        }
    }
}

// ---------------------------------------------------------------------------
// Kernel 2: per-row stats (unchanged from passing version).
// ---------------------------------------------------------------------------
__global__ __launch_bounds__(256) void k_rowstats(
    const float* __restrict__ x, const float* __restrict__ mu,
    const float* __restrict__ beta) {
    const int r = blockIdx.x;
    const int tid = threadIdx.x;
    const float* zrow;
    const float* arow;
    if (r < B_ROWS) { zrow = &g_Y[(size_t)r * DD]; arow = &x[(size_t)r * DD]; }
    else            { zrow = &g_M[(size_t)(r - B_ROWS) * DD];
                      arow = &mu[(size_t)(r - B_ROWS) * DD]; }

    float sz = 0.f, sa = 0.f, sb = 0.f;
    for (int k = tid; k < DD; k += 256) {
        float z = zrow[k], a = arow[k], bt = beta[k];
        sz += z * z;
        sa += a * a;
        sb += bt * a;
    }
    #pragma unroll
    for (int off = 16; off; off >>= 1) {
        sz += __shfl_down_sync(0xffffffffu, sz, off);
        sa += __shfl_down_sync(0xffffffffu, sa, off);
        sb += __shfl_down_sync(0xffffffffu, sb, off);
    }
    __shared__ float red[3][8];
    int w = tid / 32, lane = tid % 32;
    if (lane == 0) { red[0][w] = sz; red[1][w] = sa; red[2][w] = sb; }
    __syncthreads();
    if (tid == 0) {
        float SZ = 0.f, SA = 0.f, SB = 0.f;
        #pragma unroll
        for (int i = 0; i < 8; i++) { SZ += red[0][i]; SA += red[1][i]; SB += red[2][i]; }
        float n = SZ + EPSF * SA;
        if (r < B_ROWS) { g_nP[r] = n; g_bx[r] = SB; }
        else            { g_nQ[r - B_ROWS] = n; g_bm[r - B_ROWS] = SB; }
    }
}

// ---------------------------------------------------------------------------
// Kernel 3: G = Y @ M^T + fused epilogue (unchanged from passing version).
// ---------------------------------------------------------------------------
__global__ __launch_bounds__(128) void k_out(
    const float* __restrict__ lmbda_p, const float* __restrict__ scale_p,
    float* __restrict__ out) {
    constexpr int BK = 32;
    __shared__ float As[BK][36];
    __shared__ float Bs[BK][36];

    const int tid = threadIdx.x;
    const int ry = tid >> 3;
    const int cx = tid & 7;
    const int rowBase = blockIdx.y * 32;
    const int colBase = blockIdx.x * 32;

    float acc[2][4] = {};

    for (int k0 = 0; k0 < DD; k0 += BK) {
        #pragma unroll
        for (int i = 0; i < 2; i++) {
            int idx = tid + i * 128;
            int r = idx >> 3, kc = (idx & 7) * 4;
            float4 v = *reinterpret_cast<const float4*>(
                &g_Y[(size_t)(rowBase + r) * DD + k0 + kc]);
            As[kc + 0][r] = v.x; As[kc + 1][r] = v.y;
            As[kc + 2][r] = v.z; As[kc + 3][r] = v.w;
        }
        #pragma unroll
        for (int i = 0; i < 2; i++) {
            int idx = tid + i * 128;
            int c = idx >> 3, kc = (idx & 7) * 4;
            int gc = colBase + c;
            float4 v = make_float4(0.f, 0.f, 0.f, 0.f);
            if (gc < C_ROWS)
                v = *reinterpret_cast<const float4*>(&g_M[(size_t)gc * DD + k0 + kc]);
            Bs[kc + 0][c] = v.x; Bs[kc + 1][c] = v.y;
            Bs[kc + 2][c] = v.z; Bs[kc + 3][c] = v.w;
        }
        __syncthreads();
        #pragma unroll
        for (int kk = 0; kk < BK; kk++) {
            float a0 = As[kk][ry * 2 + 0];
            float a1 = As[kk][ry * 2 + 1];
            float4 b = *reinterpret_cast<const float4*>(&Bs[kk][cx * 4]);
            float bv[4] = {b.x, b.y, b.z, b.w};
            #pragma unroll
            for (int j = 0; j < 4; j++) {
                acc[0][j] += a0 * bv[j];
                acc[1][j] += a1 * bv[j];
            }
        }
        __syncthreads();
    }

    const float lmbda = *lmbda_p;
    const float scale = *scale_p;
    #pragma unroll
    for (int i = 0; i < 2; i++) {
        int b = rowBase + ry * 2 + i;
        float np = g_nP[b];
        float bx = g_bx[b];
        #pragma unroll
        for (int j = 0; j < 4; j++) {
            int c = colBase + cx * 4 + j;
            if (c < C_ROWS) {
                float quad = np + g_nQ[c] - 2.f * acc[i][j];
                float bd = bx - g_bm[c];
                out[(size_t)b * C_ROWS + c] =
                    -scale * (sqrtf(quad + EPSF) + lmbda * sqrtf(bd * bd + EPSF));
            }
        }
    }
}

// ---------------------------------------------------------------------------
extern "C" void kernel_launch(void* const* d_in, const int* in_sizes, int n_in,
                              void* d_out, int out_size) {
    const float* x     = (const float*)d_in[0];
    const float* mu    = (const float*)d_in[1];
    const float* beta  = (const float*)d_in[2];
    const float* L     = (const float*)d_in[3];
    const float* lmbda = (const float*)d_in[4];
    const float* scale = (const float*)d_in[5];
    float* out = (float*)d_out;

    conv_A<<<N_PAD, 256>>>(x, mu);
    conv_LT<<<dim3(16, 16), 256>>>(L);

    k1_mma<<<dim3(8, 18), 128>>>();

    k_rowstats<<<N_ROWS, 256>>>(x, mu, beta);

    k_out<<<dim3((C_ROWS + 31) / 32, B_ROWS / 32), 128>>>(lmbda, scale, out);
}

// round 7
// speedup vs baseline: 4.9369x; 1.3696x over previous
#include <cuda_runtime.h>
#include <cuda_bf16.h>
#include <cstdint>
#include <math.h>

#define DD 1024
#define B_ROWS 128
#define C_ROWS 1000
#define C_PAD 1024
#define N_ROWS (B_ROWS + C_ROWS)   // 1128
#define N_PAD 1152                 // 18 * 64
#define EPSF 1e-6f

// ---------------- scratch (__device__, no cudaMalloc; zero-initialized) ----
__device__ float g_nP[B_ROWS];
__device__ float g_bx[B_ROWS];
__device__ float g_nQ[C_ROWS];
__device__ float g_bm[C_ROWS];
__device__ float g_sa[N_ROWS];                // ||a||^2 per input row
__device__ __nv_bfloat16 g_Ah[N_PAD * DD];    // [x;mu] hi bf16 (padded rows zero)
__device__ __nv_bfloat16 g_Al[N_PAD * DD];    // [x;mu] lo bf16
__device__ __nv_bfloat16 g_BhT[DD * DD];      // tril(L)^T hi: [col][k]
__device__ __nv_bfloat16 g_BlT[DD * DD];      // tril(L)^T lo
__device__ __nv_bfloat16 g_Yh[B_ROWS * DD];   // Y = x@trilL, hi/lo bf16
__device__ __nv_bfloat16 g_Yl[B_ROWS * DD];
__device__ __nv_bfloat16 g_Mh[C_PAD * DD];    // M = mu@trilL, hi/lo (rows 1000.. stay 0)
__device__ __nv_bfloat16 g_Ml[C_PAD * DD];

// ---------------- helpers (family-generic PTX: sm_80-era) ----------------
__device__ __forceinline__ uint32_t smem_to_u32(const void* p) {
    uint32_t a;
    asm("{ .reg .u64 t; cvta.to.shared.u64 t, %1; cvt.u32.u64 %0, t; }"
        : "=r"(a) : "l"(p));
    return a;
}

#define CP16(dst, src) \
    asm volatile("cp.async.cg.shared.global [%0], [%1], 16;" \
        :: "r"(dst), "l"(src) : "memory")
#define CP_COMMIT() asm volatile("cp.async.commit_group;" ::: "memory")
#define CP_WAIT0()  asm volatile("cp.async.wait_group 0;" ::: "memory")

#define LDSM4(r0, r1, r2, r3, addr) \
    asm volatile("ldmatrix.sync.aligned.m8n8.x4.shared.b16 {%0,%1,%2,%3}, [%4];" \
        : "=r"(r0), "=r"(r1), "=r"(r2), "=r"(r3) : "r"(addr))

#define MMA16816(d, a, b) \
    asm volatile("mma.sync.aligned.m16n8k16.row.col.f32.bf16.bf16.f32 " \
        "{%0,%1,%2,%3}, {%4,%5,%6,%7}, {%8,%9}, {%0,%1,%2,%3};" \
        : "+f"((d)[0]), "+f"((d)[1]), "+f"((d)[2]), "+f"((d)[3]) \
        : "r"((a)[0]), "r"((a)[1]), "r"((a)[2]), "r"((a)[3]), \
          "r"((b)[0]), "r"((b)[1]))

__device__ __forceinline__ void split_bf16(float v, __nv_bfloat16& h, __nv_bfloat16& l) {
    h = __float2bfloat16_rn(v);
    l = __float2bfloat16_rn(v - __bfloat162float(h));
}

// ---------------------------------------------------------------------------
// conv_A: one block per row of [x;mu] (padded to 1152). Converts to bf16 hi/lo
// AND computes row stats: ||a||^2 -> g_sa, beta.a -> g_bx / g_bm.
// ---------------------------------------------------------------------------
__global__ __launch_bounds__(256) void conv_A(
    const float* __restrict__ x, const float* __restrict__ mu,
    const float* __restrict__ beta) {
    const int row = blockIdx.x;
    const int tid = threadIdx.x;
    const int c4 = tid * 4;

    float4 v = make_float4(0.f, 0.f, 0.f, 0.f);
    if (row < B_ROWS)       v = *reinterpret_cast<const float4*>(&x[(size_t)row * DD + c4]);
    else if (row < N_ROWS)  v = *reinterpret_cast<const float4*>(&mu[(size_t)(row - B_ROWS) * DD + c4]);
    float4 bt = *reinterpret_cast<const float4*>(&beta[c4]);

    float vv[4] = {v.x, v.y, v.z, v.w};
    float bb[4] = {bt.x, bt.y, bt.z, bt.w};
    __nv_bfloat16 h[4], l[4];
    float sa = 0.f, sb = 0.f;
    #pragma unroll
    for (int i = 0; i < 4; i++) {
        split_bf16(vv[i], h[i], l[i]);
        sa += vv[i] * vv[i];
        sb += bb[i] * vv[i];
    }
    *reinterpret_cast<uint2*>(&g_Ah[(size_t)row * DD + c4]) = *reinterpret_cast<uint2*>(h);
    *reinterpret_cast<uint2*>(&g_Al[(size_t)row * DD + c4]) = *reinterpret_cast<uint2*>(l);

    #pragma unroll
    for (int off = 16; off; off >>= 1) {
        sa += __shfl_down_sync(0xffffffffu, sa, off);
        sb += __shfl_down_sync(0xffffffffu, sb, off);
    }
    __shared__ float red[2][8];
    int w = tid >> 5, lane = tid & 31;
    if (lane == 0) { red[0][w] = sa; red[1][w] = sb; }
    __syncthreads();
    if (tid == 0 && row < N_ROWS) {
        float SA = 0.f, SB = 0.f;
        #pragma unroll
        for (int i = 0; i < 8; i++) { SA += red[0][i]; SB += red[1][i]; }
        g_sa[row] = SA;
        if (row < B_ROWS) g_bx[row] = SB;
        else              g_bm[row - B_ROWS] = SB;
    }
}

// ---------------------------------------------------------------------------
// conv_LT: tril(L) masked, transposed, split hi/lo.  g_BhT[col][k].
// ---------------------------------------------------------------------------
__global__ __launch_bounds__(256) void conv_LT(const float* __restrict__ L) {
    __shared__ float tile[64][65];
    const int bR = blockIdx.y * 64;   // k base
    const int bC = blockIdx.x * 64;   // col base
    const int tid = threadIdx.x;

    #pragma unroll
    for (int i = 0; i < 16; i++) {
        int idx = tid + i * 256;
        int r = idx >> 6, c = idx & 63;
        float v = L[(size_t)(bR + r) * DD + bC + c];
        if (bC + c > bR + r) v = 0.f;   // tril mask
        tile[r][c] = v;
    }
    __syncthreads();
    #pragma unroll
    for (int i = 0; i < 16; i++) {
        int idx = tid + i * 256;
        int c = idx >> 6, r = idx & 63;
        float v = tile[r][c];
        __nv_bfloat16 h, l;
        split_bf16(v, h, l);
        size_t o = (size_t)(bC + c) * DD + bR + r;
        g_BhT[o] = h;
        g_BlT[o] = l;
    }
}

// ---------------------------------------------------------------------------
// Kernel 1 (warp MMA): Z = A @ tril(L), split-bf16 3-term (hh + hl + lh).
// BM=64, BN=64, BK=32, 128 threads (2x2 warps, warp tile 32x32).
// Pair-balanced tril skip. Epilogue writes Z as bf16 hi/lo (g_Yh.. g_Ml).
// ---------------------------------------------------------------------------
#define TILE_B (64 * 40)          // bf16 elems per tile
#define STAGE_B (4 * TILE_B)

__global__ __launch_bounds__(128) void k1_mma() {
    __shared__ __align__(16) __nv_bfloat16 sm[2][STAGE_B];

    const int tid   = threadIdx.x;
    const int lane  = tid & 31;
    const int warp  = tid >> 5;
    const int warpm = warp & 1;
    const int warpn = warp >> 1;
    const int pairid  = blockIdx.x;        // 0..7
    const int rowBase = blockIdx.y * 64;

    const uint32_t smbase = smem_to_u32(sm);

    #pragma unroll 1
    for (int phase = 0; phase < 2; phase++) {
        const int ct = phase ? (15 - pairid) : pairid;
        const int colBase = ct * 64;
        const int NIT = (DD - colBase) >> 5;

        const __nv_bfloat16* srcb[8];
        uint32_t dsto[8];
        #pragma unroll
        for (int t = 0; t < 8; t++) {
            int tl  = t >> 1;
            int row = ((t & 1) << 5) + (tid >> 2);
            int c4  = tid & 3;
            const __nv_bfloat16* g;
            int grow;
            if      (tl == 0) { g = g_Ah;  grow = rowBase + row; }
            else if (tl == 1) { g = g_Al;  grow = rowBase + row; }
            else if (tl == 2) { g = g_BhT; grow = colBase + row; }
            else              { g = g_BlT; grow = colBase + row; }
            srcb[t] = g + (size_t)grow * DD + c4 * 8;
            dsto[t] = (uint32_t)(tl * (TILE_B * 2) + row * 80 + c4 * 16);
        }

        float acc[2][4][4];
        #pragma unroll
        for (int i = 0; i < 2; i++)
            #pragma unroll
            for (int j = 0; j < 4; j++)
                #pragma unroll
                for (int r = 0; r < 4; r++) acc[i][j][r] = 0.f;

        __syncthreads();

        {
            #pragma unroll
            for (int t = 0; t < 8; t++) CP16(smbase + dsto[t], srcb[t] + colBase);
            CP_COMMIT();
        }

        const uint32_t a_row_off = (uint32_t)((warpm * 32 + (lane & 15)) * 80);
        const uint32_t b_row_off = (uint32_t)((warpn * 32 + (lane & 15)) * 80);
        const uint32_t k_lane_off = (uint32_t)(((lane >> 4) & 1) * 16);

        for (int it = 0; it < NIT; it++) {
            CP_WAIT0();
            __syncthreads();
            if (it + 1 < NIT) {
                uint32_t sbn = smbase + ((it + 1) & 1) * (STAGE_B * 2);
                int k0 = colBase + (it + 1) * 32;
                #pragma unroll
                for (int t = 0; t < 8; t++) CP16(sbn + dsto[t], srcb[t] + k0);
                CP_COMMIT();
            }

            const uint32_t bufb = smbase + (it & 1) * (STAGE_B * 2);

            #pragma unroll
            for (int k16 = 0; k16 < 2; k16++) {
                const uint32_t kb = (uint32_t)(k16 * 32) + k_lane_off;

                uint32_t ah[2][4], al[2][4];
                #pragma unroll
                for (int mt = 0; mt < 2; mt++) {
                    uint32_t ad = bufb + a_row_off + (uint32_t)(mt * 16 * 80) + kb;
                    LDSM4(ah[mt][0], ah[mt][1], ah[mt][2], ah[mt][3], ad);
                    LDSM4(al[mt][0], al[mt][1], al[mt][2], al[mt][3], ad + TILE_B * 2);
                }
                uint32_t bh[4][2], bl[4][2];
                #pragma unroll
                for (int nt2 = 0; nt2 < 2; nt2++) {
                    uint32_t bd = bufb + 2 * (TILE_B * 2) + b_row_off
                                + (uint32_t)(nt2 * 16 * 80) + kb;
                    uint32_t r0, r1, r2, r3;
                    LDSM4(r0, r1, r2, r3, bd);
                    bh[nt2 * 2 + 0][0] = r0; bh[nt2 * 2 + 0][1] = r2;
                    bh[nt2 * 2 + 1][0] = r1; bh[nt2 * 2 + 1][1] = r3;
                    LDSM4(r0, r1, r2, r3, bd + TILE_B * 2);
                    bl[nt2 * 2 + 0][0] = r0; bl[nt2 * 2 + 0][1] = r2;
                    bl[nt2 * 2 + 1][0] = r1; bl[nt2 * 2 + 1][1] = r3;
                }
                #pragma unroll
                for (int mt = 0; mt < 2; mt++)
                    #pragma unroll
                    for (int nt = 0; nt < 4; nt++) {
                        MMA16816(acc[mt][nt], ah[mt], bh[nt]);
                        MMA16816(acc[mt][nt], ah[mt], bl[nt]);
                        MMA16816(acc[mt][nt], al[mt], bh[nt]);
                    }
            }
        }

        // epilogue: split Z to bf16 hi/lo and store
        #pragma unroll
        for (int mt = 0; mt < 2; mt++) {
            #pragma unroll
            for (int nt = 0; nt < 4; nt++) {
                int gm = rowBase + warpm * 32 + mt * 16 + (lane >> 2);
                int gn = colBase + warpn * 32 + nt * 8 + (lane & 3) * 2;
                #pragma unroll
                for (int h = 0; h < 2; h++) {
                    int gr = gm + h * 8;
                    float v0 = acc[mt][nt][h * 2], v1 = acc[mt][nt][h * 2 + 1];
                    __nv_bfloat16 h0, l0, h1, l1;
                    split_bf16(v0, h0, l0);
                    split_bf16(v1, h1, l1);
                    __nv_bfloat162 hh, ll;
                    hh.x = h0; hh.y = h1; ll.x = l0; ll.y = l1;
                    if (gr < B_ROWS) {
                        *reinterpret_cast<__nv_bfloat162*>(&g_Yh[(size_t)gr * DD + gn]) = hh;
                        *reinterpret_cast<__nv_bfloat162*>(&g_Yl[(size_t)gr * DD + gn]) = ll;
                    } else if (gr < N_ROWS) {
                        size_t o = (size_t)(gr - B_ROWS) * DD + gn;
                        *reinterpret_cast<__nv_bfloat162*>(&g_Mh[o]) = hh;
                        *reinterpret_cast<__nv_bfloat162*>(&g_Ml[o]) = ll;
                    }
                }
            }
        }
    }
}

// ---------------------------------------------------------------------------
// rowstats (slim): ||z||^2 only, from bf16 hi/lo; combines with g_sa.
// ---------------------------------------------------------------------------
__global__ __launch_bounds__(256) void k_rowstats() {
    const int r = blockIdx.x;
    const int tid = threadIdx.x;
    const __nv_bfloat16* hrow;
    const __nv_bfloat16* lrow;
    if (r < B_ROWS) { hrow = &g_Yh[(size_t)r * DD]; lrow = &g_Yl[(size_t)r * DD]; }
    else { hrow = &g_Mh[(size_t)(r - B_ROWS) * DD]; lrow = &g_Ml[(size_t)(r - B_ROWS) * DD]; }

    const int k4 = tid * 4;
    uint2 hu = *reinterpret_cast<const uint2*>(&hrow[k4]);
    uint2 lu = *reinterpret_cast<const uint2*>(&lrow[k4]);
    const __nv_bfloat16* hp = reinterpret_cast<const __nv_bfloat16*>(&hu);
    const __nv_bfloat16* lp = reinterpret_cast<const __nv_bfloat16*>(&lu);
    float sz = 0.f;
    #pragma unroll
    for (int i = 0; i < 4; i++) {
        float y = __bfloat162float(hp[i]) + __bfloat162float(lp[i]);
        sz += y * y;
    }
    #pragma unroll
    for (int off = 16; off; off >>= 1)
        sz += __shfl_down_sync(0xffffffffu, sz, off);
    __shared__ float red[8];
    int w = tid >> 5, lane = tid & 31;
    if (lane == 0) red[w] = sz;
    __syncthreads();
    if (tid == 0) {
        float SZ = 0.f;
        #pragma unroll
        for (int i = 0; i < 8; i++) SZ += red[i];
        float n = SZ + EPSF * g_sa[r];
        if (r < B_ROWS) g_nP[r] = n;
        else            g_nQ[r - B_ROWS] = n;
    }
}

// ---------------------------------------------------------------------------
// k_out (warp MMA): G = Y @ M^T via 3-term split-bf16, fused epilogue.
// BM=32, BN=32, BK=32, 128 threads (2x2 warps, warp tile 16x16).
// Grid (32, 4) = 128 blocks. K = 1024 (32 iters).
// ---------------------------------------------------------------------------
#define KO_TILE 1280              // 32 * 40 bf16 elems per tile
#define KO_STAGE (4 * KO_TILE)

__global__ __launch_bounds__(128) void k_out_mma(
    const float* __restrict__ lmbda_p, const float* __restrict__ scale_p,
    float* __restrict__ out) {
    __shared__ __align__(16) __nv_bfloat16 sm[2][KO_STAGE];

    const int tid   = threadIdx.x;
    const int lane  = tid & 31;
    const int warp  = tid >> 5;
    const int warpm = warp & 1;
    const int warpn = warp >> 1;
    const int rowBase = blockIdx.y * 32;   // b
    const int colBase = blockIdx.x * 32;   // c

    const uint32_t smbase = smem_to_u32(sm);

    // 4 chunks of 16B per thread per stage (512 chunks total)
    const __nv_bfloat16* srcb[4];
    uint32_t dsto[4];
    #pragma unroll
    for (int t = 0; t < 4; t++) {
        int ci = tid + t * 128;           // 0..511
        int tl = ci >> 7;                 // 0..3: Yh, Yl, Mh, Ml
        int row = (ci & 127) >> 2;        // 0..31
        int c4  = ci & 3;
        const __nv_bfloat16* g;
        int grow;
        if      (tl == 0) { g = g_Yh; grow = rowBase + row; }
        else if (tl == 1) { g = g_Yl; grow = rowBase + row; }
        else if (tl == 2) { g = g_Mh; grow = colBase + row; }
        else              { g = g_Ml; grow = colBase + row; }
        srcb[t] = g + (size_t)grow * DD + c4 * 8;
        dsto[t] = (uint32_t)(tl * (KO_TILE * 2) + row * 80 + c4 * 16);
    }

    float acc[2][4];
    #pragma unroll
    for (int j = 0; j < 2; j++)
        #pragma unroll
        for (int r = 0; r < 4; r++) acc[j][r] = 0.f;

    {
        #pragma unroll
        for (int t = 0; t < 4; t++) CP16(smbase + dsto[t], srcb[t]);
        CP_COMMIT();
    }

    const uint32_t a_row_off = (uint32_t)((warpm * 16 + (lane & 15)) * 80);
    const uint32_t b_row_off = (uint32_t)((warpn * 16 + (lane & 15)) * 80);
    const uint32_t k_lane_off = (uint32_t)(((lane >> 4) & 1) * 16);

    const int NIT = DD / 32;   // 32
    for (int it = 0; it < NIT; it++) {
        CP_WAIT0();
        __syncthreads();
        if (it + 1 < NIT) {
            uint32_t sbn = smbase + ((it + 1) & 1) * (KO_STAGE * 2);
            int k0 = (it + 1) * 32;
            #pragma unroll
            for (int t = 0; t < 4; t++) CP16(sbn + dsto[t], srcb[t] + k0);
            CP_COMMIT();
        }
        const uint32_t bufb = smbase + (it & 1) * (KO_STAGE * 2);

        #pragma unroll
        for (int k16 = 0; k16 < 2; k16++) {
            const uint32_t kb = (uint32_t)(k16 * 32) + k_lane_off;

            uint32_t ah[4], al[4];
            {
                uint32_t ad = bufb + a_row_off + kb;
                LDSM4(ah[0], ah[1], ah[2], ah[3], ad);
                LDSM4(al[0], al[1], al[2], al[3], ad + KO_TILE * 2);
            }
            uint32_t bh[2][2], bl[2][2];
            {
                uint32_t bd = bufb + 2 * (KO_TILE * 2) + b_row_off + kb;
                uint32_t r0, r1, r2, r3;
                LDSM4(r0, r1, r2, r3, bd);
                bh[0][0] = r0; bh[0][1] = r2;
                bh[1][0] = r1; bh[1][1] = r3;
                LDSM4(r0, r1, r2, r3, bd + KO_TILE * 2);
                bl[0][0] = r0; bl[0][1] = r2;
                bl[1][0] = r1; bl[1][1] = r3;
            }
            #pragma unroll
            for (int nt = 0; nt < 2; nt++) {
                MMA16816(acc[nt], ah, bh[nt]);
                MMA16816(acc[nt], ah, bl[nt]);
                MMA16816(acc[nt], al, bh[nt]);
            }
        }
    }

    // fused epilogue
    const float lmbda = *lmbda_p;
    const float scale = *scale_p;
    #pragma unroll
    for (int nt = 0; nt < 2; nt++) {
        int gm = rowBase + warpm * 16 + (lane >> 2);
        int gn = colBase + warpn * 16 + nt * 8 + (lane & 3) * 2;
        #pragma unroll
        for (int h = 0; h < 2; h++) {
            int b = gm + h * 8;
            float np = g_nP[b];
            float bx = g_bx[b];
            #pragma unroll
            for (int e = 0; e < 2; e++) {
                int c = gn + e;
                if (c < C_ROWS) {
                    float G = acc[nt][h * 2 + e];
                    float quad = np + g_nQ[c] - 2.f * G;
                    float bd = bx - g_bm[c];
                    out[(size_t)b * C_ROWS + c] =
                        -scale * (sqrtf(quad + EPSF) + lmbda * sqrtf(bd * bd + EPSF));
                }
            }
        }
    }
}

// ---------------------------------------------------------------------------
extern "C" void kernel_launch(void* const* d_in, const int* in_sizes, int n_in,
                              void* d_out, int out_size) {
    const float* x     = (const float*)d_in[0];
    const float* mu    = (const float*)d_in[1];
    const float* beta  = (const float*)d_in[2];
    const float* L     = (const float*)d_in[3];
    const float* lmbda = (const float*)d_in[4];
    const float* scale = (const float*)d_in[5];
    float* out = (float*)d_out;

    conv_A<<<N_PAD, 256>>>(x, mu, beta);
    conv_LT<<<dim3(16, 16), 256>>>(L);

    k1_mma<<<dim3(8, 18), 128>>>();

    k_rowstats<<<N_ROWS, 256>>>();

    k_out_mma<<<dim3(32, 4), 128>>>(lmbda, scale, out);
}

// round 13
// speedup vs baseline: 5.1560x; 1.0444x over previous
#include <cuda_runtime.h>
#include <cuda_bf16.h>
#include <cstdint>
#include <math.h>

#define DD 1024
#define B_ROWS 128
#define C_ROWS 1000
#define C_PAD 1024
#define N_ROWS (B_ROWS + C_ROWS)   // 1128
#define N_PAD 1152                 // 18 * 64
#define EPSF 1e-6f

// ---------------- scratch (__device__, zero-initialized) ----------------
__device__ float g_nP[B_ROWS];
__device__ float g_bx[B_ROWS];
__device__ float g_nQ[C_ROWS];
__device__ float g_bm[C_ROWS];
__device__ float g_sa[N_ROWS];                // ||a||^2 per input row (fp32)
__device__ float g_partZ[16][N_PAD];          // per-coltile partial ||z||^2
__device__ __nv_bfloat16 g_Ah[N_PAD * DD];    // [x;mu] hi bf16 (padded rows zero)
__device__ __nv_bfloat16 g_Al[N_PAD * DD];    // [x;mu] lo bf16
__device__ __nv_bfloat16 g_BhT[DD * DD];      // tril(L)^T hi: [col][k]
__device__ __nv_bfloat16 g_BlT[DD * DD];      // tril(L)^T lo
__device__ __nv_bfloat16 g_Yh[B_ROWS * DD];   // Y = x@trilL, hi bf16 only
__device__ __nv_bfloat16 g_Mh[C_PAD * DD];    // M = mu@trilL, hi (rows 1000.. stay 0)

// ---------------- helpers (family-generic PTX: sm_80-era) ----------------
__device__ __forceinline__ uint32_t smem_to_u32(const void* p) {
    uint32_t a;
    asm("{ .reg .u64 t; cvta.to.shared.u64 t, %1; cvt.u32.u64 %0, t; }"
        : "=r"(a) : "l"(p));
    return a;
}

#define CP16(dst, src) \
    asm volatile("cp.async.cg.shared.global [%0], [%1], 16;" \
        :: "r"(dst), "l"(src) : "memory")
#define CP_COMMIT() asm volatile("cp.async.commit_group;" ::: "memory")
#define CP_WAIT0()  asm volatile("cp.async.wait_group 0;" ::: "memory")

#define LDSM4(r0, r1, r2, r3, addr) \
    asm volatile("ldmatrix.sync.aligned.m8n8.x4.shared.b16 {%0,%1,%2,%3}, [%4];" \
        : "=r"(r0), "=r"(r1), "=r"(r2), "=r"(r3) : "r"(addr))

#define MMA16816(d, a, b) \
    asm volatile("mma.sync.aligned.m16n8k16.row.col.f32.bf16.bf16.f32 " \
        "{%0,%1,%2,%3}, {%4,%5,%6,%7}, {%8,%9}, {%0,%1,%2,%3};" \
        : "+f"((d)[0]), "+f"((d)[1]), "+f"((d)[2]), "+f"((d)[3]) \
        : "r"((a)[0]), "r"((a)[1]), "r"((a)[2]), "r"((a)[3]), \
          "r"((b)[0]), "r"((b)[1]))

__device__ __forceinline__ void split_bf16(float v, __nv_bfloat16& h, __nv_bfloat16& l) {
    h = __float2bfloat16_rn(v);
    l = __float2bfloat16_rn(v - __bfloat162float(h));
}

// ---------------------------------------------------------------------------
// conv_A: one block per row of [x;mu]. bf16 hi/lo + stats (||a||^2, beta.a).
// ---------------------------------------------------------------------------
__global__ __launch_bounds__(256) void conv_A(
    const float* __restrict__ x, const float* __restrict__ mu,
    const float* __restrict__ beta) {
    const int row = blockIdx.x;
    const int tid = threadIdx.x;
    const int c4 = tid * 4;

    float4 v = make_float4(0.f, 0.f, 0.f, 0.f);
    if (row < B_ROWS)       v = *reinterpret_cast<const float4*>(&x[(size_t)row * DD + c4]);
    else if (row < N_ROWS)  v = *reinterpret_cast<const float4*>(&mu[(size_t)(row - B_ROWS) * DD + c4]);
    float4 bt = *reinterpret_cast<const float4*>(&beta[c4]);

    float vv[4] = {v.x, v.y, v.z, v.w};
    float bb[4] = {bt.x, bt.y, bt.z, bt.w};
    __nv_bfloat16 h[4], l[4];
    float sa = 0.f, sb = 0.f;
    #pragma unroll
    for (int i = 0; i < 4; i++) {
        split_bf16(vv[i], h[i], l[i]);
        sa += vv[i] * vv[i];
        sb += bb[i] * vv[i];
    }
    *reinterpret_cast<uint2*>(&g_Ah[(size_t)row * DD + c4]) = *reinterpret_cast<uint2*>(h);
    *reinterpret_cast<uint2*>(&g_Al[(size_t)row * DD + c4]) = *reinterpret_cast<uint2*>(l);

    #pragma unroll
    for (int off = 16; off; off >>= 1) {
        sa += __shfl_down_sync(0xffffffffu, sa, off);
        sb += __shfl_down_sync(0xffffffffu, sb, off);
    }
    __shared__ float red[2][8];
    int w = tid >> 5, lane = tid & 31;
    if (lane == 0) { red[0][w] = sa; red[1][w] = sb; }
    __syncthreads();
    if (tid == 0 && row < N_ROWS) {
        float SA = 0.f, SB = 0.f;
        #pragma unroll
        for (int i = 0; i < 8; i++) { SA += red[0][i]; SB += red[1][i]; }
        g_sa[row] = SA;
        if (row < B_ROWS) g_bx[row] = SB;
        else              g_bm[row - B_ROWS] = SB;
    }
}

// ---------------------------------------------------------------------------
// conv_LT: tril(L) masked, transposed, split hi/lo.  g_BhT[col][k].
// ---------------------------------------------------------------------------
__global__ __launch_bounds__(256) void conv_LT(const float* __restrict__ L) {
    __shared__ float tile[64][65];
    const int bR = blockIdx.y * 64;   // k base
    const int bC = blockIdx.x * 64;   // col base
    const int tid = threadIdx.x;

    #pragma unroll
    for (int i = 0; i < 16; i++) {
        int idx = tid + i * 256;
        int r = idx >> 6, c = idx & 63;
        float v = L[(size_t)(bR + r) * DD + bC + c];
        if (bC + c > bR + r) v = 0.f;   // tril mask
        tile[r][c] = v;
    }
    __syncthreads();
    #pragma unroll
    for (int i = 0; i < 16; i++) {
        int idx = tid + i * 256;
        int c = idx >> 6, r = idx & 63;
        float v = tile[r][c];
        __nv_bfloat16 h, l;
        split_bf16(v, h, l);
        size_t o = (size_t)(bC + c) * DD + bR + r;
        g_BhT[o] = h;
        g_BlT[o] = l;
    }
}

// ---------------------------------------------------------------------------
// Kernel 1 (warp MMA): Z = A @ tril(L), split-bf16 3-term (hh + hl + lh).
// BM=64, BN=64, BK=32, 128 threads. Pair-balanced tril skip.
// Epilogue: exact fp32 row-norm partials -> g_partZ; Z stored as bf16 hi only.
// ---------------------------------------------------------------------------
#define TILE_B (64 * 40)
#define STAGE_B (4 * TILE_B)

__global__ __launch_bounds__(128) void k1_mma() {
    __shared__ __align__(16) __nv_bfloat16 sm[2][STAGE_B];
    __shared__ float zred[64][8];

    const int tid   = threadIdx.x;
    const int lane  = tid & 31;
    const int warp  = tid >> 5;
    const int warpm = warp & 1;
    const int warpn = warp >> 1;
    const int pairid  = blockIdx.x;        // 0..7
    const int rowBase = blockIdx.y * 64;

    const uint32_t smbase = smem_to_u32(sm);

    #pragma unroll 1
    for (int phase = 0; phase < 2; phase++) {
        const int ct = phase ? (15 - pairid) : pairid;
        const int colBase = ct * 64;
        const int NIT = (DD - colBase) >> 5;

        const __nv_bfloat16* srcb[8];
        uint32_t dsto[8];
        #pragma unroll
        for (int t = 0; t < 8; t++) {
            int tl  = t >> 1;
            int row = ((t & 1) << 5) + (tid >> 2);
            int c4  = tid & 3;
            const __nv_bfloat16* g;
            int grow;
            if      (tl == 0) { g = g_Ah;  grow = rowBase + row; }
            else if (tl == 1) { g = g_Al;  grow = rowBase + row; }
            else if (tl == 2) { g = g_BhT; grow = colBase + row; }
            else              { g = g_BlT; grow = colBase + row; }
            srcb[t] = g + (size_t)grow * DD + c4 * 8;
            dsto[t] = (uint32_t)(tl * (TILE_B * 2) + row * 80 + c4 * 16);
        }

        float acc[2][4][4];
        #pragma unroll
        for (int i = 0; i < 2; i++)
            #pragma unroll
            for (int j = 0; j < 4; j++)
                #pragma unroll
                for (int r = 0; r < 4; r++) acc[i][j][r] = 0.f;

        __syncthreads();   // protect smem (tiles + zred) across phases

        {
            #pragma unroll
            for (int t = 0; t < 8; t++) CP16(smbase + dsto[t], srcb[t] + colBase);
            CP_COMMIT();
        }

        const uint32_t a_row_off = (uint32_t)((warpm * 32 + (lane & 15)) * 80);
        const uint32_t b_row_off = (uint32_t)((warpn * 32 + (lane & 15)) * 80);
        const uint32_t k_lane_off = (uint32_t)(((lane >> 4) & 1) * 16);

        for (int it = 0; it < NIT; it++) {
            CP_WAIT0();
            __syncthreads();
            if (it + 1 < NIT) {
                uint32_t sbn = smbase + ((it + 1) & 1) * (STAGE_B * 2);
                int k0 = colBase + (it + 1) * 32;
                #pragma unroll
                for (int t = 0; t < 8; t++) CP16(sbn + dsto[t], srcb[t] + k0);
                CP_COMMIT();
            }

            const uint32_t bufb = smbase + (it & 1) * (STAGE_B * 2);

            #pragma unroll
            for (int k16 = 0; k16 < 2; k16++) {
                const uint32_t kb = (uint32_t)(k16 * 32) + k_lane_off;

                uint32_t ah[2][4], al[2][4];
                #pragma unroll
                for (int mt = 0; mt < 2; mt++) {
                    uint32_t ad = bufb + a_row_off + (uint32_t)(mt * 16 * 80) + kb;
                    LDSM4(ah[mt][0], ah[mt][1], ah[mt][2], ah[mt][3], ad);
                    LDSM4(al[mt][0], al[mt][1], al[mt][2], al[mt][3], ad + TILE_B * 2);
                }
                uint32_t bh[4][2], bl[4][2];
                #pragma unroll
                for (int nt2 = 0; nt2 < 2; nt2++) {
                    uint32_t bd = bufb + 2 * (TILE_B * 2) + b_row_off
                                + (uint32_t)(nt2 * 16 * 80) + kb;
                    uint32_t r0, r1, r2, r3;
                    LDSM4(r0, r1, r2, r3, bd);
                    bh[nt2 * 2 + 0][0] = r0; bh[nt2 * 2 + 0][1] = r2;
                    bh[nt2 * 2 + 1][0] = r1; bh[nt2 * 2 + 1][1] = r3;
                    LDSM4(r0, r1, r2, r3, bd + TILE_B * 2);
                    bl[nt2 * 2 + 0][0] = r0; bl[nt2 * 2 + 0][1] = r2;
                    bl[nt2 * 2 + 1][0] = r1; bl[nt2 * 2 + 1][1] = r3;
                }
                #pragma unroll
                for (int mt = 0; mt < 2; mt++)
                    #pragma unroll
                    for (int nt = 0; nt < 4; nt++) {
                        MMA16816(acc[mt][nt], ah[mt], bh[nt]);
                        MMA16816(acc[mt][nt], ah[mt], bl[nt]);
                        MMA16816(acc[mt][nt], al[mt], bh[nt]);
                    }
            }
        }

        // ---- epilogue: exact fp32 row-norm partials + bf16-hi store ----
        const int pidx = (warpn << 2) | (lane & 3);
        #pragma unroll
        for (int mt = 0; mt < 2; mt++) {
            #pragma unroll
            for (int h = 0; h < 2; h++) {
                int rl = warpm * 32 + mt * 16 + (lane >> 2) + h * 8;
                float s = 0.f;
                #pragma unroll
                for (int nt = 0; nt < 4; nt++) {
                    float v0 = acc[mt][nt][h * 2], v1 = acc[mt][nt][h * 2 + 1];
                    s += v0 * v0 + v1 * v1;
                }
                zred[rl][pidx] = s;
            }
        }

        #pragma unroll
        for (int mt = 0; mt < 2; mt++) {
            #pragma unroll
            for (int nt = 0; nt < 4; nt++) {
                int gm = rowBase + warpm * 32 + mt * 16 + (lane >> 2);
                int gn = colBase + warpn * 32 + nt * 8 + (lane & 3) * 2;
                #pragma unroll
                for (int h = 0; h < 2; h++) {
                    int gr = gm + h * 8;
                    __nv_bfloat162 hh;
                    hh.x = __float2bfloat16_rn(acc[mt][nt][h * 2]);
                    hh.y = __float2bfloat16_rn(acc[mt][nt][h * 2 + 1]);
                    if (gr < B_ROWS)
                        *reinterpret_cast<__nv_bfloat162*>(&g_Yh[(size_t)gr * DD + gn]) = hh;
                    else if (gr < N_ROWS)
                        *reinterpret_cast<__nv_bfloat162*>(&g_Mh[(size_t)(gr - B_ROWS) * DD + gn]) = hh;
                }
            }
        }

        __syncthreads();
        if (tid < 64) {
            float s = 0.f;
            #pragma unroll
            for (int p = 0; p < 8; p++) s += zred[tid][p];
            g_partZ[ct][rowBase + tid] = s;
        }
    }
}

// ---------------------------------------------------------------------------
// k_norm: combine 16 coltile partials + eps*||a||^2 -> g_nP / g_nQ.
// ---------------------------------------------------------------------------
__global__ __launch_bounds__(256) void k_norm() {
    int r = blockIdx.x * 256 + threadIdx.x;
    if (r < N_ROWS) {
        float s = 0.f;
        #pragma unroll
        for (int ct = 0; ct < 16; ct++) s += g_partZ[ct][r];
        float n = s + EPSF * g_sa[r];
        if (r < B_ROWS) g_nP[r] = n;
        else            g_nQ[r - B_ROWS] = n;
    }
}

// ---------------------------------------------------------------------------
// k_out (warp MMA): G = Yh @ Mh^T (hi terms only), fused epilogue.
// BM=32, BN=32, BK=32, 128 threads. Grid (32, 4) = 128 blocks.
// ---------------------------------------------------------------------------
#define KO_TILE 1280              // 32 * 40 bf16 elems per tile
#define KO_STAGE (2 * KO_TILE)    // Yh, Mh only

__global__ __launch_bounds__(128) void k_out_mma(
    const float* __restrict__ lmbda_p, const float* __restrict__ scale_p,
    float* __restrict__ out) {
    __shared__ __align__(16) __nv_bfloat16 sm[2][KO_STAGE];

    const int tid   = threadIdx.x;
    const int lane  = tid & 31;
    const int warp  = tid >> 5;
    const int warpm = warp & 1;
    const int warpn = warp >> 1;
    const int rowBase = blockIdx.y * 32;   // b
    const int colBase = blockIdx.x * 32;   // c

    const uint32_t smbase = smem_to_u32(sm);

    const __nv_bfloat16* srcb[2];
    uint32_t dsto[2];
    #pragma unroll
    for (int t = 0; t < 2; t++) {
        int ci = tid + t * 128;           // 0..255
        int tl = ci >> 7;                 // 0: Yh, 1: Mh
        int row = (ci & 127) >> 2;        // 0..31
        int c4  = ci & 3;
        const __nv_bfloat16* g;
        int grow;
        if (tl == 0) { g = g_Yh; grow = rowBase + row; }
        else         { g = g_Mh; grow = colBase + row; }
        srcb[t] = g + (size_t)grow * DD + c4 * 8;
        dsto[t] = (uint32_t)(tl * (KO_TILE * 2) + row * 80 + c4 * 16);
    }

    float acc[2][4];
    #pragma unroll
    for (int j = 0; j < 2; j++)
        #pragma unroll
        for (int r = 0; r < 4; r++) acc[j][r] = 0.f;

    {
        #pragma unroll
        for (int t = 0; t < 2; t++) CP16(smbase + dsto[t], srcb[t]);
        CP_COMMIT();
    }

    const uint32_t a_row_off = (uint32_t)((warpm * 16 + (lane & 15)) * 80);
    const uint32_t b_row_off = (uint32_t)((warpn * 16 + (lane & 15)) * 80);
    const uint32_t k_lane_off = (uint32_t)(((lane >> 4) & 1) * 16);

    const int NIT = DD / 32;   // 32
    for (int it = 0; it < NIT; it++) {
        CP_WAIT0();
        __syncthreads();
        if (it + 1 < NIT) {
            uint32_t sbn = smbase + ((it + 1) & 1) * (KO_STAGE * 2);
            int k0 = (it + 1) * 32;
            #pragma unroll
            for (int t = 0; t < 2; t++) CP16(sbn + dsto[t], srcb[t] + k0);
            CP_COMMIT();
        }
        const uint32_t bufb = smbase + (it & 1) * (KO_STAGE * 2);

        #pragma unroll
        for (int k16 = 0; k16 < 2; k16++) {
            const uint32_t kb = (uint32_t)(k16 * 32) + k_lane_off;

            uint32_t ah[4];
            LDSM4(ah[0], ah[1], ah[2], ah[3], bufb + a_row_off + kb);

            uint32_t bh[2][2];
            {
                uint32_t r0, r1, r2, r3;
                LDSM4(r0, r1, r2, r3, bufb + (KO_TILE * 2) + b_row_off + kb);
                bh[0][0] = r0; bh[0][1] = r2;
                bh[1][0] = r1; bh[1][1] = r3;
            }
            #pragma unroll
            for (int nt = 0; nt < 2; nt++)
                MMA16816(acc[nt], ah, bh[nt]);
        }
    }

    // fused epilogue
    const float lmbda = *lmbda_p;
    const float scale = *scale_p;
    #pragma unroll
    for (int nt = 0; nt < 2; nt++) {
        int gm = rowBase + warpm * 16 + (lane >> 2);
        int gn = colBase + warpn * 16 + nt * 8 + (lane & 3) * 2;
        #pragma unroll
        for (int h = 0; h < 2; h++) {
            int b = gm + h * 8;
            float np = g_nP[b];
            float bx = g_bx[b];
            #pragma unroll
            for (int e = 0; e < 2; e++) {
                int c = gn + e;
                if (c < C_ROWS) {
                    float G = acc[nt][h * 2 + e];
                    float quad = np + g_nQ[c] - 2.f * G;
                    float bd = bx - g_bm[c];
                    out[(size_t)b * C_ROWS + c] =
                        -scale * (sqrtf(quad + EPSF) + lmbda * sqrtf(bd * bd + EPSF));
                }
            }
        }
    }
}

// ---------------------------------------------------------------------------
extern "C" void kernel_launch(void* const* d_in, const int* in_sizes, int n_in,
                              void* d_out, int out_size) {
    const float* x     = (const float*)d_in[0];
    const float* mu    = (const float*)d_in[1];
    const float* beta  = (const float*)d_in[2];
    const float* L     = (const float*)d_in[3];
    const float* lmbda = (const float*)d_in[4];
    const float* scale = (const float*)d_in[5];
    float* out = (float*)d_out;

    conv_A<<<N_PAD, 256>>>(x, mu, beta);
    conv_LT<<<dim3(16, 16), 256>>>(L);

    k1_mma<<<dim3(8, 18), 128>>>();

    k_norm<<<(N_ROWS + 255) / 256, 256>>>();

    k_out_mma<<<dim3(32, 4), 128>>>(lmbda, scale, out);
}